// round 1
// baseline (speedup 1.0000x reference)
#include <cuda_runtime.h>
#include <math.h>

// Scratch state (no allocations allowed).
__device__ double g_quad_sum;
__device__ double g_const;
__device__ float  g_mu_post[16];
__device__ float  g_coeff[24];  // 8 blocks * (S00, S01, S11)

// ---------------------------------------------------------------------------
// Kernel 1: all the tiny 16x16 (= 8 x 2x2 block) linear algebra, single thread.
// ---------------------------------------------------------------------------
__global__ void setup_kernel(const float* __restrict__ mu_like,
                             const float* __restrict__ pose,
                             const float* __restrict__ sp,
                             const float* __restrict__ sl,
                             long long n) {
    if (blockIdx.x != 0 || threadIdx.x != 0) return;

    g_quad_sum = 0.0;

    // _transform_mu: rotate interleaved points about centroid, translate.
    double px[8], py[8], cx = 0.0, cy = 0.0;
    for (int i = 0; i < 8; i++) {
        px[i] = (double)mu_like[2 * i];
        py[i] = (double)mu_like[2 * i + 1];
        cx += px[i]; cy += py[i];
    }
    cx *= 0.125; cy *= 0.125;
    double th = (double)pose[2];
    double ct = cos(th), st = sin(th);
    double tx = (double)pose[0], ty = (double)pose[1];
    double mup[16];
    for (int i = 0; i < 8; i++) {
        double x = px[i] - cx, y = py[i] - cy;
        mup[2 * i]     = ct * x - st * y + tx;
        mup[2 * i + 1] = st * x + ct * y + ty;
    }

    double logdet = 0.0;
    for (int b = 0; b < 8; b++) {
        const float* pp = sp + 4 * b;   // prior block params [[p0,p1],[p2,p3]]
        const float* pl = sl + 4 * b;   // likelihood block params

        // cov = B B^T + eps I  (2x2 symmetric), then precision = inverse
        double p0 = pp[0], p1 = pp[1], p2 = pp[2], p3 = pp[3];
        double cp00 = p0 * p0 + p1 * p1 + 1e-6;
        double cp01 = p0 * p2 + p1 * p3;
        double cp11 = p2 * p2 + p3 * p3 + 1e-6;
        double dp = cp00 * cp11 - cp01 * cp01;
        double Pp00 =  cp11 / dp, Pp01 = -cp01 / dp, Pp11 = cp00 / dp;

        double q0 = pl[0], q1 = pl[1], q2 = pl[2], q3 = pl[3];
        double cl00 = q0 * q0 + q1 * q1 + 1e-6;
        double cl01 = q0 * q2 + q1 * q3;
        double cl11 = q2 * q2 + q3 * q3 + 1e-6;
        double dl = cl00 * cl11 - cl01 * cl01;
        double Pl00 =  cl11 / dl, Pl01 = -cl01 / dl, Pl11 = cl00 / dl;

        // posterior precision block Q, its logdet, and Sigma_post block S = Q^{-1}
        double Q00 = Pp00 + Pl00, Q01 = Pp01 + Pl01, Q11 = Pp11 + Pl11;
        double dq = Q00 * Q11 - Q01 * Q01;
        logdet += log(dq);
        double S00 =  Q11 / dq, S01 = -Q01 / dq, S11 = Q00 / dq;

        // mu_post block = S @ (P_prior @ mu_prior + P_like @ mu_like)
        double mlx = (double)mu_like[2 * b], mly = (double)mu_like[2 * b + 1];
        double mpx = mup[2 * b], mpy = mup[2 * b + 1];
        double vx = Pp00 * mpx + Pp01 * mpy + Pl00 * mlx + Pl01 * mly;
        double vy = Pp01 * mpx + Pp11 * mpy + Pl01 * mlx + Pl11 * mly;
        g_mu_post[2 * b]     = (float)(S00 * vx + S01 * vy);
        g_mu_post[2 * b + 1] = (float)(S01 * vx + S11 * vy);
        g_coeff[3 * b + 0] = (float)S00;
        g_coeff[3 * b + 1] = (float)S01;
        g_coeff[3 * b + 2] = (float)S11;
    }

    // result = N*(0.5*32*log(2pi) + 0.5*logdet) + 0.5*sum(quad)
    g_const = (double)n * (16.0 * log(2.0 * M_PI) + 0.5 * logdet);
}

// ---------------------------------------------------------------------------
// Kernel 2: HBM-bound streaming reduction over 2M x 16 floats.
// Each float4 holds two complete (x,y) pairs -> quad form is local to it.
// Stride is a multiple of 4, so each thread's block-pair class is fixed.
// ---------------------------------------------------------------------------
__global__ void __launch_bounds__(256)
quad_reduce_kernel(const float4* __restrict__ obs4, long long n4) {
    long long t = (long long)blockIdx.x * blockDim.x + threadIdx.x;
    long long stride = (long long)gridDim.x * blockDim.x;  // multiple of 4

    int cls = (int)(t & 3);          // which float4 of the row
    int blk = 2 * cls;               // first of two 2x2 blocks covered
    float m0 = g_mu_post[4 * cls + 0];
    float m1 = g_mu_post[4 * cls + 1];
    float m2 = g_mu_post[4 * cls + 2];
    float m3 = g_mu_post[4 * cls + 3];
    float a0 = g_coeff[3 * blk + 0], b0 = g_coeff[3 * blk + 1], c0 = g_coeff[3 * blk + 2];
    float a1 = g_coeff[3 * blk + 3], b1 = g_coeff[3 * blk + 4], c1 = g_coeff[3 * blk + 5];
    float tb0 = 2.0f * b0, tb1 = 2.0f * b1;

    float acc = 0.0f;
    for (long long i = t; i < n4; i += stride) {
        float4 v = obs4[i];
        float d0 = v.x - m0, d1 = v.y - m1, d2 = v.z - m2, d3 = v.w - m3;
        float q;
        q = a0 * d0 * d0;
        q = fmaf(tb0 * d0, d1, q);
        q = fmaf(c0 * d1, d1, q);
        q = fmaf(a1 * d2, d2, q);
        q = fmaf(tb1 * d2, d3, q);
        q = fmaf(c1 * d3, d3, q);
        acc += q;
    }

    // warp reduce in double
    double dacc = (double)acc;
    #pragma unroll
    for (int o = 16; o > 0; o >>= 1)
        dacc += __shfl_down_sync(0xffffffffu, dacc, o);

    __shared__ double warp_sums[8];
    int lane = threadIdx.x & 31, wid = threadIdx.x >> 5;
    if (lane == 0) warp_sums[wid] = dacc;
    __syncthreads();
    if (wid == 0) {
        double s = (lane < 8) ? warp_sums[lane] : 0.0;
        #pragma unroll
        for (int o = 4; o > 0; o >>= 1)
            s += __shfl_down_sync(0xffffffffu, s, o);
        if (lane == 0) atomicAdd(&g_quad_sum, s);
    }
}

// ---------------------------------------------------------------------------
// Kernel 3: finalize scalar output.
// ---------------------------------------------------------------------------
__global__ void finalize_kernel(float* __restrict__ out) {
    if (blockIdx.x == 0 && threadIdx.x == 0) {
        out[0] = (float)(g_const + 0.5 * g_quad_sum);
    }
}

extern "C" void kernel_launch(void* const* d_in, const int* in_sizes, int n_in,
                              void* d_out, int out_size) {
    const float* obs      = (const float*)d_in[0];
    const float* mu_like  = (const float*)d_in[1];
    const float* pose     = (const float*)d_in[2];
    const float* sp       = (const float*)d_in[3];
    const float* sl       = (const float*)d_in[4];
    float* out = (float*)d_out;

    long long n  = (long long)in_sizes[0] / 16;   // number of observations
    long long n4 = n * 4;                          // number of float4s

    setup_kernel<<<1, 1>>>(mu_like, pose, sp, sl, n);

    int blocks = 1184;  // 8 * 148 SMs
    quad_reduce_kernel<<<blocks, 256>>>((const float4*)obs, n4);

    finalize_kernel<<<1, 1>>>(out);
}

// round 2
// speedup vs baseline: 2.0853x; 2.0853x over previous
#include <cuda_runtime.h>
#include <math.h>

// Scratch (no allocations allowed): per-block partials + completion counter.
__device__ double g_partials[2048];
__device__ unsigned int g_counter = 0;

__device__ __forceinline__ float quad_eval(float4 v, float m0, float m1, float m2, float m3,
                                           float a0, float tb0, float c0,
                                           float a1, float tb1, float c1) {
    float d0 = v.x - m0, d1 = v.y - m1, d2 = v.z - m2, d3 = v.w - m3;
    float q = a0 * d0 * d0;
    q = fmaf(tb0 * d0, d1, q);
    q = fmaf(c0 * d1, d1, q);
    q = fmaf(a1 * d2, d2, q);
    q = fmaf(tb1 * d2, d3, q);
    q = fmaf(c1 * d3, d3, q);
    return q;
}

__global__ void __launch_bounds__(256)
fused_kernel(const float4* __restrict__ obs4,
             const float* __restrict__ mu_like,
             const float* __restrict__ pose,
             const float* __restrict__ sp,
             const float* __restrict__ sl,
             long long n4, long long n,
             float* __restrict__ out) {
    __shared__ float s_mu[16];
    __shared__ float s_cf[24];     // 8 blocks * (S00, S01, S11)
    __shared__ float s_logdet;
    __shared__ bool  s_is_last;
    __shared__ double s_warp[8];

    const int tid = threadIdx.x;

    // ---- per-block redundant setup: 8 lanes, one 2x2 block each (float, like ref) ----
    if (tid < 8) {
        const int b = tid;
        // centroid of the 8 interleaved (x,y) points via width-8 shuffles
        float pxv = mu_like[2 * b], pyv = mu_like[2 * b + 1];
        float cx = pxv, cy = pyv;
        #pragma unroll
        for (int o = 4; o > 0; o >>= 1) {
            cx += __shfl_xor_sync(0xffu, cx, o, 8);
            cy += __shfl_xor_sync(0xffu, cy, o, 8);
        }
        cx *= 0.125f; cy *= 0.125f;

        float st, ct;
        sincosf(pose[2], &st, &ct);
        float mpx = ct * (pxv - cx) - st * (pyv - cy) + pose[0];
        float mpy = st * (pxv - cx) + ct * (pyv - cy) + pose[1];

        // prior block precision
        float p0 = sp[4 * b + 0], p1 = sp[4 * b + 1], p2 = sp[4 * b + 2], p3 = sp[4 * b + 3];
        float cp00 = p0 * p0 + p1 * p1 + 1e-6f;
        float cp01 = p0 * p2 + p1 * p3;
        float cp11 = p2 * p2 + p3 * p3 + 1e-6f;
        float rdp = 1.0f / (cp00 * cp11 - cp01 * cp01);
        float Pp00 =  cp11 * rdp, Pp01 = -cp01 * rdp, Pp11 = cp00 * rdp;

        // likelihood block precision
        float q0 = sl[4 * b + 0], q1 = sl[4 * b + 1], q2 = sl[4 * b + 2], q3 = sl[4 * b + 3];
        float cl00 = q0 * q0 + q1 * q1 + 1e-6f;
        float cl01 = q0 * q2 + q1 * q3;
        float cl11 = q2 * q2 + q3 * q3 + 1e-6f;
        float rdl = 1.0f / (cl00 * cl11 - cl01 * cl01);
        float Pl00 =  cl11 * rdl, Pl01 = -cl01 * rdl, Pl11 = cl00 * rdl;

        // posterior precision block, logdet, Sigma_post block
        float Q00 = Pp00 + Pl00, Q01 = Pp01 + Pl01, Q11 = Pp11 + Pl11;
        float dq = Q00 * Q11 - Q01 * Q01;
        float ld = logf(dq);
        #pragma unroll
        for (int o = 4; o > 0; o >>= 1)
            ld += __shfl_xor_sync(0xffu, ld, o, 8);
        if (b == 0) s_logdet = ld;

        float rdq = 1.0f / dq;
        float S00 =  Q11 * rdq, S01 = -Q01 * rdq, S11 = Q00 * rdq;

        // mu_post block = S @ (P_prior @ mu_prior + P_like @ mu_like)
        float vx = Pp00 * mpx + Pp01 * mpy + Pl00 * pxv + Pl01 * pyv;
        float vy = Pp01 * mpx + Pp11 * mpy + Pl01 * pxv + Pl11 * pyv;
        s_mu[2 * b]     = S00 * vx + S01 * vy;
        s_mu[2 * b + 1] = S01 * vx + S11 * vy;
        s_cf[3 * b + 0] = S00;
        s_cf[3 * b + 1] = S01;
        s_cf[3 * b + 2] = S11;
    }
    __syncthreads();

    // ---- streaming quad-form reduction ----
    const long long t = (long long)blockIdx.x * blockDim.x + tid;
    const long long stride = (long long)gridDim.x * blockDim.x;  // multiple of 4

    const int cls = tid & 3;        // which float4 within a 16-float row
    const int blk = 2 * cls;        // covers 2x2 blocks blk and blk+1
    const float m0 = s_mu[4 * cls + 0], m1 = s_mu[4 * cls + 1];
    const float m2 = s_mu[4 * cls + 2], m3 = s_mu[4 * cls + 3];
    const float a0 = s_cf[3 * blk + 0], tb0 = 2.0f * s_cf[3 * blk + 1], c0 = s_cf[3 * blk + 2];
    const float a1 = s_cf[3 * blk + 3], tb1 = 2.0f * s_cf[3 * blk + 4], c1 = s_cf[3 * blk + 5];

    float acc0 = 0.0f, acc1 = 0.0f, acc2 = 0.0f, acc3 = 0.0f;
    long long i = t;
    for (; i + 3 * stride < n4; i += 4 * stride) {
        float4 v0 = __ldcs(&obs4[i]);
        float4 v1 = __ldcs(&obs4[i + stride]);
        float4 v2 = __ldcs(&obs4[i + 2 * stride]);
        float4 v3 = __ldcs(&obs4[i + 3 * stride]);
        acc0 += quad_eval(v0, m0, m1, m2, m3, a0, tb0, c0, a1, tb1, c1);
        acc1 += quad_eval(v1, m0, m1, m2, m3, a0, tb0, c0, a1, tb1, c1);
        acc2 += quad_eval(v2, m0, m1, m2, m3, a0, tb0, c0, a1, tb1, c1);
        acc3 += quad_eval(v3, m0, m1, m2, m3, a0, tb0, c0, a1, tb1, c1);
    }
    for (; i < n4; i += stride)
        acc0 += quad_eval(__ldcs(&obs4[i]), m0, m1, m2, m3, a0, tb0, c0, a1, tb1, c1);

    // ---- block reduction in double ----
    double dacc = (double)acc0 + (double)acc1 + (double)acc2 + (double)acc3;
    #pragma unroll
    for (int o = 16; o > 0; o >>= 1)
        dacc += __shfl_down_sync(0xffffffffu, dacc, o);

    const int lane = tid & 31, wid = tid >> 5;
    if (lane == 0) s_warp[wid] = dacc;
    __syncthreads();
    if (wid == 0) {
        double s = (lane < 8) ? s_warp[lane] : 0.0;
        #pragma unroll
        for (int o = 4; o > 0; o >>= 1)
            s += __shfl_down_sync(0xffffffffu, s, o);
        if (lane == 0) g_partials[blockIdx.x] = s;
    }

    // ---- last-block finalize ----
    if (tid == 0) {
        __threadfence();
        unsigned int c = atomicAdd(&g_counter, 1u);
        s_is_last = (c == gridDim.x - 1);
    }
    __syncthreads();
    if (s_is_last) {
        double s = 0.0;
        for (int k = tid; k < gridDim.x; k += blockDim.x)
            s += g_partials[k];
        #pragma unroll
        for (int o = 16; o > 0; o >>= 1)
            s += __shfl_down_sync(0xffffffffu, s, o);
        if (lane == 0) s_warp[wid] = s;
        __syncthreads();
        if (wid == 0) {
            double tot = (lane < 8) ? s_warp[lane] : 0.0;
            #pragma unroll
            for (int o = 4; o > 0; o >>= 1)
                tot += __shfl_down_sync(0xffffffffu, tot, o);
            if (lane == 0) {
                // N*(16*log(2pi) + 0.5*logdet) + 0.5*quad_sum
                double cst = (double)n * (16.0 * 1.8378770664093453 + 0.5 * (double)s_logdet);
                out[0] = (float)(cst + 0.5 * tot);
                g_counter = 0;  // reset for next graph replay
            }
        }
    }
}

extern "C" void kernel_launch(void* const* d_in, const int* in_sizes, int n_in,
                              void* d_out, int out_size) {
    const float* obs     = (const float*)d_in[0];
    const float* mu_like = (const float*)d_in[1];
    const float* pose    = (const float*)d_in[2];
    const float* sp      = (const float*)d_in[3];
    const float* sl      = (const float*)d_in[4];
    float* out = (float*)d_out;

    long long n  = (long long)in_sizes[0] / 16;
    long long n4 = n * 4;

    const int blocks = 1184;  // 8 * 148 SMs, multiple of 4 threads-per-class
    fused_kernel<<<blocks, 256>>>((const float4*)obs, mu_like, pose, sp, sl, n4, n, out);
}

// round 3
// speedup vs baseline: 2.8554x; 1.3693x over previous
#include <cuda_runtime.h>
#include <math.h>

// Scratch (no allocations allowed): per-block partials + completion counter.
__device__ double g_partials[1024];
__device__ unsigned int g_counter = 0;

#define NBLOCKS 592   // one full wave: 4 blocks/SM * 148 SMs (32-warp cap)

__device__ __forceinline__ float quad_eval(float4 v, float m0, float m1, float m2, float m3,
                                           float a0, float tb0, float c0,
                                           float a1, float tb1, float c1) {
    float d0 = v.x - m0, d1 = v.y - m1, d2 = v.z - m2, d3 = v.w - m3;
    float q = a0 * d0 * d0;
    q = fmaf(tb0 * d0, d1, q);
    q = fmaf(c0 * d1, d1, q);
    q = fmaf(a1 * d2, d2, q);
    q = fmaf(tb1 * d2, d3, q);
    q = fmaf(c1 * d3, d3, q);
    return q;
}

__global__ void __launch_bounds__(256, 4)
fused_kernel(const float4* __restrict__ obs4,
             const float* __restrict__ mu_like,
             const float* __restrict__ pose,
             const float* __restrict__ sp,
             const float* __restrict__ sl,
             long long n4, long long n,
             float* __restrict__ out) {
    __shared__ float s_mu[16];
    __shared__ float s_cf[24];     // 8 blocks * (S00, S01, S11)
    __shared__ float s_logdet;
    __shared__ bool  s_is_last;
    __shared__ double s_warp[8];

    const int tid = threadIdx.x;

    // ---- per-block redundant setup: 8 lanes, one 2x2 block each ----
    if (tid < 8) {
        const int b = tid;
        float pxv = mu_like[2 * b], pyv = mu_like[2 * b + 1];
        float cx = pxv, cy = pyv;
        #pragma unroll
        for (int o = 4; o > 0; o >>= 1) {
            cx += __shfl_xor_sync(0xffu, cx, o, 8);
            cy += __shfl_xor_sync(0xffu, cy, o, 8);
        }
        cx *= 0.125f; cy *= 0.125f;

        float st, ct;
        sincosf(pose[2], &st, &ct);
        float mpx = ct * (pxv - cx) - st * (pyv - cy) + pose[0];
        float mpy = st * (pxv - cx) + ct * (pyv - cy) + pose[1];

        float p0 = sp[4 * b + 0], p1 = sp[4 * b + 1], p2 = sp[4 * b + 2], p3 = sp[4 * b + 3];
        float cp00 = p0 * p0 + p1 * p1 + 1e-6f;
        float cp01 = p0 * p2 + p1 * p3;
        float cp11 = p2 * p2 + p3 * p3 + 1e-6f;
        float rdp = 1.0f / (cp00 * cp11 - cp01 * cp01);
        float Pp00 =  cp11 * rdp, Pp01 = -cp01 * rdp, Pp11 = cp00 * rdp;

        float q0 = sl[4 * b + 0], q1 = sl[4 * b + 1], q2 = sl[4 * b + 2], q3 = sl[4 * b + 3];
        float cl00 = q0 * q0 + q1 * q1 + 1e-6f;
        float cl01 = q0 * q2 + q1 * q3;
        float cl11 = q2 * q2 + q3 * q3 + 1e-6f;
        float rdl = 1.0f / (cl00 * cl11 - cl01 * cl01);
        float Pl00 =  cl11 * rdl, Pl01 = -cl01 * rdl, Pl11 = cl00 * rdl;

        float Q00 = Pp00 + Pl00, Q01 = Pp01 + Pl01, Q11 = Pp11 + Pl11;
        float dq = Q00 * Q11 - Q01 * Q01;
        float ld = logf(dq);
        #pragma unroll
        for (int o = 4; o > 0; o >>= 1)
            ld += __shfl_xor_sync(0xffu, ld, o, 8);
        if (b == 0) s_logdet = ld;

        float rdq = 1.0f / dq;
        float S00 =  Q11 * rdq, S01 = -Q01 * rdq, S11 = Q00 * rdq;

        float vx = Pp00 * mpx + Pp01 * mpy + Pl00 * pxv + Pl01 * pyv;
        float vy = Pp01 * mpx + Pp11 * mpy + Pl01 * pxv + Pl11 * pyv;
        s_mu[2 * b]     = S00 * vx + S01 * vy;
        s_mu[2 * b + 1] = S01 * vx + S11 * vy;
        s_cf[3 * b + 0] = S00;
        s_cf[3 * b + 1] = S01;
        s_cf[3 * b + 2] = S11;
    }
    __syncthreads();

    // ---- streaming quad-form reduction, 8 loads in flight per thread ----
    const long long t = (long long)blockIdx.x * blockDim.x + tid;
    const long long stride = (long long)NBLOCKS * 256;  // multiple of 4

    const int cls = tid & 3;
    const int blk = 2 * cls;
    const float m0 = s_mu[4 * cls + 0], m1 = s_mu[4 * cls + 1];
    const float m2 = s_mu[4 * cls + 2], m3 = s_mu[4 * cls + 3];
    const float a0 = s_cf[3 * blk + 0], tb0 = 2.0f * s_cf[3 * blk + 1], c0 = s_cf[3 * blk + 2];
    const float a1 = s_cf[3 * blk + 3], tb1 = 2.0f * s_cf[3 * blk + 4], c1 = s_cf[3 * blk + 5];

    float acc0 = 0.0f, acc1 = 0.0f, acc2 = 0.0f, acc3 = 0.0f;
    long long i = t;
    for (; i + 7 * stride < n4; i += 8 * stride) {
        float4 v0 = __ldcs(&obs4[i]);
        float4 v1 = __ldcs(&obs4[i + stride]);
        float4 v2 = __ldcs(&obs4[i + 2 * stride]);
        float4 v3 = __ldcs(&obs4[i + 3 * stride]);
        float4 v4 = __ldcs(&obs4[i + 4 * stride]);
        float4 v5 = __ldcs(&obs4[i + 5 * stride]);
        float4 v6 = __ldcs(&obs4[i + 6 * stride]);
        float4 v7 = __ldcs(&obs4[i + 7 * stride]);
        acc0 += quad_eval(v0, m0, m1, m2, m3, a0, tb0, c0, a1, tb1, c1);
        acc1 += quad_eval(v1, m0, m1, m2, m3, a0, tb0, c0, a1, tb1, c1);
        acc2 += quad_eval(v2, m0, m1, m2, m3, a0, tb0, c0, a1, tb1, c1);
        acc3 += quad_eval(v3, m0, m1, m2, m3, a0, tb0, c0, a1, tb1, c1);
        acc0 += quad_eval(v4, m0, m1, m2, m3, a0, tb0, c0, a1, tb1, c1);
        acc1 += quad_eval(v5, m0, m1, m2, m3, a0, tb0, c0, a1, tb1, c1);
        acc2 += quad_eval(v6, m0, m1, m2, m3, a0, tb0, c0, a1, tb1, c1);
        acc3 += quad_eval(v7, m0, m1, m2, m3, a0, tb0, c0, a1, tb1, c1);
    }
    for (; i < n4; i += stride)
        acc0 += quad_eval(__ldcs(&obs4[i]), m0, m1, m2, m3, a0, tb0, c0, a1, tb1, c1);

    // ---- block reduction in double ----
    double dacc = (double)acc0 + (double)acc1 + (double)acc2 + (double)acc3;
    #pragma unroll
    for (int o = 16; o > 0; o >>= 1)
        dacc += __shfl_down_sync(0xffffffffu, dacc, o);

    const int lane = tid & 31, wid = tid >> 5;
    if (lane == 0) s_warp[wid] = dacc;
    __syncthreads();
    if (wid == 0) {
        double s = (lane < 8) ? s_warp[lane] : 0.0;
        #pragma unroll
        for (int o = 4; o > 0; o >>= 1)
            s += __shfl_down_sync(0xffffffffu, s, o);
        if (lane == 0) g_partials[blockIdx.x] = s;
    }

    // ---- last-block finalize ----
    if (tid == 0) {
        __threadfence();
        unsigned int c = atomicAdd(&g_counter, 1u);
        s_is_last = (c == gridDim.x - 1);
    }
    __syncthreads();
    if (s_is_last) {
        double s = 0.0;
        for (int k = tid; k < gridDim.x; k += blockDim.x)
            s += g_partials[k];
        #pragma unroll
        for (int o = 16; o > 0; o >>= 1)
            s += __shfl_down_sync(0xffffffffu, s, o);
        if (lane == 0) s_warp[wid] = s;
        __syncthreads();
        if (wid == 0) {
            double tot = (lane < 8) ? s_warp[lane] : 0.0;
            #pragma unroll
            for (int o = 4; o > 0; o >>= 1)
                tot += __shfl_down_sync(0xffffffffu, tot, o);
            if (lane == 0) {
                double cst = (double)n * (16.0 * 1.8378770664093453 + 0.5 * (double)s_logdet);
                out[0] = (float)(cst + 0.5 * tot);
                g_counter = 0;  // reset for next graph replay
            }
        }
    }
}

extern "C" void kernel_launch(void* const* d_in, const int* in_sizes, int n_in,
                              void* d_out, int out_size) {
    const float* obs     = (const float*)d_in[0];
    const float* mu_like = (const float*)d_in[1];
    const float* pose    = (const float*)d_in[2];
    const float* sp      = (const float*)d_in[3];
    const float* sl      = (const float*)d_in[4];
    float* out = (float*)d_out;

    long long n  = (long long)in_sizes[0] / 16;
    long long n4 = n * 4;

    fused_kernel<<<NBLOCKS, 256>>>((const float4*)obs, mu_like, pose, sp, sl, n4, n, out);
}